// round 7
// baseline (speedup 1.0000x reference)
#include <cuda_runtime.h>
#include <math.h>

// x: 4096x4096 fp32 = 16,777,216 elements. 64-elem quant blocks.
// Fused single-wave persistent kernel: 592 CTAs x 256 threads, 4 CTAs/SM
// guaranteed resident (registers capped by launch_bounds), so an in-kernel
// flag-spin grid barrier is deadlock-free.
#define GRID   592
#define TOTW   (GRID * 8)        // total warps = 4736
#define MAXT   10                // max tiles supported (7 needed for 4096^2)

__device__ float    g_pmin[GRID];
__device__ float    g_pmax[GRID];
__device__ float    g_smin;
__device__ float    g_ss;
__device__ int      g_cond;
__device__ unsigned g_ctr;       // phase-1 arrival counter  (returns to 0)
__device__ unsigned g_done;      // completion counter       (returns to 0)
__device__ volatile unsigned g_flag;  // scales-ready flag    (returns to 0)

// Branchless insertion of v into descending top-5.
__device__ __forceinline__ void ins5(float v, float& t0, float& t1, float& t2,
                                     float& t3, float& t4) {
    float hi, lo;
    hi = fmaxf(t0, v); lo = fminf(t0, v); t0 = hi; v = lo;
    hi = fmaxf(t1, v); lo = fminf(t1, v); t1 = hi; v = lo;
    hi = fmaxf(t2, v); lo = fminf(t2, v); t2 = hi; v = lo;
    hi = fmaxf(t3, v); lo = fminf(t3, v); t3 = hi; v = lo;
    t4 = fmaxf(t4, v);
}

// Merge partner lane's sorted top-5 (shfl.bfly) into mine; progressive start
// levels since partner's list is sorted. 5 SHFL + 25 FMNMX.
__device__ __forceinline__ void merge_bfly(int m, float& t0, float& t1,
                                           float& t2, float& t3, float& t4) {
    const unsigned FULL = 0xFFFFFFFFu;
    float b0 = __shfl_xor_sync(FULL, t0, m);
    float b1 = __shfl_xor_sync(FULL, t1, m);
    float b2 = __shfl_xor_sync(FULL, t2, m);
    float b3 = __shfl_xor_sync(FULL, t3, m);
    float b4 = __shfl_xor_sync(FULL, t4, m);
    float hi, lo, v;
    hi = fmaxf(t0, b0); lo = fminf(t0, b0); t0 = hi; v = lo;
    hi = fmaxf(t1, v);  lo = fminf(t1, v);  t1 = hi; v = lo;
    hi = fmaxf(t2, v);  lo = fminf(t2, v);  t2 = hi; v = lo;
    hi = fmaxf(t3, v);  lo = fminf(t3, v);  t3 = hi; v = lo;
    t4 = fmaxf(t4, v);
    hi = fmaxf(t1, b1); lo = fminf(t1, b1); t1 = hi; v = lo;
    hi = fmaxf(t2, v);  lo = fminf(t2, v);  t2 = hi; v = lo;
    hi = fmaxf(t3, v);  lo = fminf(t3, v);  t3 = hi; v = lo;
    t4 = fmaxf(t4, v);
    hi = fmaxf(t2, b2); lo = fminf(t2, b2); t2 = hi; v = lo;
    hi = fmaxf(t3, v);  lo = fminf(t3, v);  t3 = hi; v = lo;
    t4 = fmaxf(t4, v);
    hi = fmaxf(t3, b3); lo = fminf(t3, b3); t3 = hi; v = lo;
    t4 = fmaxf(t4, v);
    t4 = fmaxf(t4, b4);
}

// 4-bit code: magnitude levels {0.75,1,1.5,2,3} = 1-mantissa-bit fp32 grid.
// clamp |q| to [0.75,3], +0x1FFFFF (round-half-down = positive argmin tie),
// exponent+msb -> level 1..5; level 0 if |q|<=0.375; bit3 = sign.
__device__ __forceinline__ unsigned code1(float x, float rs) {
    float q = __fmul_rn(x, rs);
    float a = fabsf(q);
    float m = fminf(fmaxf(a, 0.75f), 3.0f);
    unsigned lv = ((__float_as_uint(m) + 0x001FFFFFu) >> 22) - 0xFCu;  // 1..5
    lv = (a > 0.375f) ? lv : 0u;
    return lv | ((__float_as_uint(q) >> 28) & 8u);
}

// Decode: mag*4 in {0,3,4,6,8,12} packed as nibbles of an immediate.
__device__ __forceinline__ float dec1(unsigned nib, float dq4) {
    float mag4 = (float)((0x00C86430u >> ((nib & 7u) << 2)) & 0xFu);
    float v = __fmul_rn(mag4, dq4);
    return __uint_as_float(__float_as_uint(v) | ((nib & 8u) << 28));
}

__global__ void __launch_bounds__(256, 4)
kFused(const float4* __restrict__ in4, float4* __restrict__ out4,
       int n4, int num_blocks, int ntiles) {
    __shared__ float wmin[8], wmax[8];
    __shared__ float rmin[256], rmax[256];
    __shared__ int   s_last;

    const int tid  = threadIdx.x;
    const int lane = tid & 31;
    const int warp = tid >> 5;
    const int w    = blockIdx.x * 8 + warp;      // global warp id

    unsigned cw[MAXT][2];
    float    sarr[MAXT];
    float    mn = 3.402823466e38f, mx = 0.0f;

    // ---------------- Phase 1: scales + codes (one read of x) -------------
    for (int t = 0; t < ntiles; t++) {
        int f4b = (t * TOTW + w) * 128 + lane * 4;   // 4 consecutive f4/lane
        float4 z = make_float4(0.f, 0.f, 0.f, 0.f);
        float4 v0 = (f4b + 0 < n4) ? in4[f4b + 0] : z;
        float4 v1 = (f4b + 1 < n4) ? in4[f4b + 1] : z;
        float4 v2 = (f4b + 2 < n4) ? in4[f4b + 2] : z;
        float4 v3 = (f4b + 3 < n4) ? in4[f4b + 3] : z;

        float t0 = 0.f, t1 = 0.f, t2 = 0.f, t3 = 0.f, t4 = 0.f;
        ins5(fabsf(v0.x), t0, t1, t2, t3, t4);
        ins5(fabsf(v0.y), t0, t1, t2, t3, t4);
        ins5(fabsf(v0.z), t0, t1, t2, t3, t4);
        ins5(fabsf(v0.w), t0, t1, t2, t3, t4);
        ins5(fabsf(v1.x), t0, t1, t2, t3, t4);
        ins5(fabsf(v1.y), t0, t1, t2, t3, t4);
        ins5(fabsf(v1.z), t0, t1, t2, t3, t4);
        ins5(fabsf(v1.w), t0, t1, t2, t3, t4);
        ins5(fabsf(v2.x), t0, t1, t2, t3, t4);
        ins5(fabsf(v2.y), t0, t1, t2, t3, t4);
        ins5(fabsf(v2.z), t0, t1, t2, t3, t4);
        ins5(fabsf(v2.w), t0, t1, t2, t3, t4);
        ins5(fabsf(v3.x), t0, t1, t2, t3, t4);
        ins5(fabsf(v3.y), t0, t1, t2, t3, t4);
        ins5(fabsf(v3.z), t0, t1, t2, t3, t4);
        ins5(fabsf(v3.w), t0, t1, t2, t3, t4);

        merge_bfly(1, t0, t1, t2, t3, t4);
        merge_bfly(2, t0, t1, t2, t3, t4);   // block top-5 in all 4 lanes

        // jnp.quantile linear: a[59]*(1-frac)+a[60]*frac, frac=fp32(.95*63)-59
        const float FRAC = 0.95f * 63.0f - 59.0f;
        const float OMF  = 1.0f - FRAC;
        float s = __fadd_rn(__fmul_rn(t4, OMF), __fmul_rn(t3, FRAC));
        s = fmaxf(s, 1e-8f);
        sarr[t] = s;

        float rs = __frcp_rn(s);
        cw[t][0] =  code1(v0.x, rs)        | (code1(v0.y, rs) << 4)
                 | (code1(v0.z, rs) << 8)  | (code1(v0.w, rs) << 12)
                 | (code1(v1.x, rs) << 16) | (code1(v1.y, rs) << 20)
                 | (code1(v1.z, rs) << 24) | (code1(v1.w, rs) << 28);
        cw[t][1] =  code1(v2.x, rs)        | (code1(v2.y, rs) << 4)
                 | (code1(v2.z, rs) << 8)  | (code1(v2.w, rs) << 12)
                 | (code1(v3.x, rs) << 16) | (code1(v3.y, rs) << 20)
                 | (code1(v3.z, rs) << 24) | (code1(v3.w, rs) << 28);

        int b = (t * TOTW + w) * 8 + (lane >> 2);
        if (b < num_blocks) { mn = fminf(mn, s); mx = fmaxf(mx, s); }
    }

    // CTA-level min/max reduce
    #pragma unroll
    for (int m = 16; m > 0; m >>= 1) {
        mn = fminf(mn, __shfl_xor_sync(0xFFFFFFFFu, mn, m));
        mx = fmaxf(mx, __shfl_xor_sync(0xFFFFFFFFu, mx, m));
    }
    if (lane == 0) { wmin[warp] = mn; wmax[warp] = mx; }
    __syncthreads();
    if (tid == 0) {
        float cmn = wmin[0], cmx = wmax[0];
        #pragma unroll
        for (int k = 1; k < 8; k++) {
            cmn = fminf(cmn, wmin[k]);
            cmx = fmaxf(cmx, wmax[k]);
        }
        __stcg(&g_pmin[blockIdx.x], cmn);
        __stcg(&g_pmax[blockIdx.x], cmx);
        __threadfence();
        s_last = (atomicAdd(&g_ctr, 1u) == (unsigned)(gridDim.x - 1));
    }
    __syncthreads();

    // ---------------- Grid barrier: last CTA publishes, rest spin ---------
    if (s_last) {
        float fmn = 3.402823466e38f, fmx = 0.0f;
        for (int i = tid; i < GRID; i += 256) {
            fmn = fminf(fmn, __ldcg(&g_pmin[i]));
            fmx = fmaxf(fmx, __ldcg(&g_pmax[i]));
        }
        rmin[tid] = fmn; rmax[tid] = fmx;
        __syncthreads();
        #pragma unroll
        for (int off = 128; off > 0; off >>= 1) {
            if (tid < off) {
                rmin[tid] = fminf(rmin[tid], rmin[tid + off]);
                rmax[tid] = fmaxf(rmax[tid], rmax[tid + off]);
            }
            __syncthreads();
        }
        if (tid == 0) {
            float smin = rmin[0], smax = rmax[0];
            int cond = (smax > smin);
            g_smin = smin;
            g_cond = cond;
            g_ss = cond ? __fdiv_rn(__fsub_rn(smax, smin), 255.0f) : 1.0f;
            g_ctr = 0u;                       // reset for next graph replay
            __threadfence();
            g_flag = 1u;
        }
        __syncthreads();
    } else {
        if (tid == 0) {
            while (g_flag == 0u) __nanosleep(64);
            __threadfence();
        }
        __syncthreads();
    }

    const float smin = g_smin;
    const float ss   = g_ss;
    const int   cond = g_cond;

    // ---------------- Phase 2: decode + write ------------------------------
    for (int t = 0; t < ntiles; t++) {
        float s = sarr[t];
        float qv = 0.0f;
        if (cond) {
            qv = rintf(__fdiv_rn(__fsub_rn(s, smin), ss));  // half-even round
            qv = fminf(fmaxf(qv, 0.0f), 255.0f);
        }
        float dq4 = __fmul_rn(qv, ss) * 0.25f;  // deq*0.25 (smin dropped: ref)

        int f4b = (t * TOTW + w) * 128 + lane * 4;
        unsigned c0 = cw[t][0], c1 = cw[t][1];
        float4 o;
        if (f4b + 0 < n4) {
            o.x = dec1(c0,       dq4); o.y = dec1(c0 >> 4,  dq4);
            o.z = dec1(c0 >> 8,  dq4); o.w = dec1(c0 >> 12, dq4);
            __stcs(&out4[f4b + 0], o);
        }
        if (f4b + 1 < n4) {
            o.x = dec1(c0 >> 16, dq4); o.y = dec1(c0 >> 20, dq4);
            o.z = dec1(c0 >> 24, dq4); o.w = dec1(c0 >> 28, dq4);
            __stcs(&out4[f4b + 1], o);
        }
        if (f4b + 2 < n4) {
            o.x = dec1(c1,       dq4); o.y = dec1(c1 >> 4,  dq4);
            o.z = dec1(c1 >> 8,  dq4); o.w = dec1(c1 >> 12, dq4);
            __stcs(&out4[f4b + 2], o);
        }
        if (f4b + 3 < n4) {
            o.x = dec1(c1 >> 16, dq4); o.y = dec1(c1 >> 20, dq4);
            o.z = dec1(c1 >> 24, dq4); o.w = dec1(c1 >> 28, dq4);
            __stcs(&out4[f4b + 3], o);
        }
    }

    // ---------------- Cleanup: last finisher resets the flag --------------
    if (tid == 0) {
        __threadfence();
        if (atomicAdd(&g_done, 1u) == (unsigned)(gridDim.x - 1)) {
            g_done = 0u;
            g_flag = 0u;
        }
    }
}

extern "C" void kernel_launch(void* const* d_in, const int* in_sizes, int n_in,
                              void* d_out, int out_size) {
    const float* x = (const float*)d_in[0];
    float* out = (float*)d_out;
    int n = in_sizes[0];

    int n4 = n >> 2;                       // n is a multiple of 4 (4096x4096)
    int num_blocks = (n + 63) >> 6;
    int per_tile = TOTW * 128;             // f4 covered per tile
    int ntiles = (n4 + per_tile - 1) / per_tile;
    if (ntiles > MAXT) ntiles = MAXT;      // fixed shape needs 7

    kFused<<<GRID, 256>>>((const float4*)x, (float4*)out, n4, num_blocks,
                          ntiles);
}

// round 8
// speedup vs baseline: 1.2624x; 1.2624x over previous
#include <cuda_runtime.h>
#include <math.h>

// x: 4096x4096 fp32 = 16,777,216 elements -> 262,144 blocks of 64.
#define MAXB   262144
#define MAXGA  8192

__device__ float  g_scales[MAXB];
__device__ float2 g_info2[MAXB];    // {1/s (RN), deq_scale}
__device__ float  g_pmin[MAXGA];
__device__ float  g_pmax[MAXGA];
__device__ float  g_smin;
__device__ float  g_ss;
__device__ int    g_cond;
__device__ unsigned g_ctr;          // last-CTA election (returns to 0 each run)

__device__ __forceinline__ void ce(float& a, float& b) {
    float hi = fmaxf(a, b);
    b = fminf(a, b);
    a = hi;
}

// sort4 descending: classic 5-comparator network.
__device__ __forceinline__ void sort4(float& s0, float& s1, float& s2, float& s3) {
    ce(s0, s1); ce(s2, s3); ce(s0, s2); ce(s1, s3); ce(s1, s2);
}

// Odd-even merge: two sorted-desc-4 -> sorted-desc top-5 (13 ops).
__device__ __forceinline__ void merge44_top5(
    float a0, float a1, float a2, float a3,
    float b0, float b1, float b2, float b3,
    float& r0, float& r1, float& r2, float& r3, float& r4) {
    float e0 = fmaxf(a0, b0), x = fminf(a0, b0);
    float y  = fmaxf(a2, b2);
    float e1 = fmaxf(x, y),  e2 = fminf(x, y);
    float o0 = fmaxf(a1, b1), xp = fminf(a1, b1);
    float yp = fmaxf(a3, b3);
    float o1 = fmaxf(xp, yp);
    r0 = e0;
    r1 = fmaxf(o0, e1); r2 = fminf(o0, e1);
    r3 = fmaxf(o1, e2); r4 = fminf(o1, e2);
}

// Odd-even merge: two sorted-desc-5 -> sorted-desc top-5 (15 ops).
__device__ __forceinline__ void merge55_top5(
    float a0, float a1, float a2, float a3, float a4,
    float b0, float b1, float b2, float b3, float b4,
    float& r0, float& r1, float& r2, float& r3, float& r4) {
    // evens (a0,a2,a4)+(b0,b2,b4): need e0,e1,e2
    float f0 = fmaxf(a0, b0), x = fminf(a0, b0);
    float y  = fmaxf(a4, b4);
    float f1 = fmaxf(x, y);
    float g0 = fmaxf(a2, b2);
    float e1 = fmaxf(g0, f1), e2 = fminf(g0, f1);
    // odds (a1,a3)+(b1,b3): need o0,o1
    float o0 = fmaxf(a1, b1), xp = fminf(a1, b1);
    float yp = fmaxf(a3, b3);
    float o1 = fmaxf(xp, yp);
    r0 = f0;
    r1 = fmaxf(o0, e1); r2 = fminf(o0, e1);
    r3 = fmaxf(o1, e2); r4 = fminf(o1, e2);
}

// Final merge of two sorted-desc-5, producing ONLY ranks 3 and 4 (10 ops).
__device__ __forceinline__ void merge55_r34(
    float a0, float a1, float a2, float a3, float a4,
    float b0, float b1, float b2, float b3, float b4,
    float& w3, float& w4) {
    float x  = fminf(a0, b0);
    float y  = fmaxf(a4, b4);
    float f1 = fmaxf(x, y);
    float g0 = fmaxf(a2, b2);
    float e2 = fminf(g0, f1);
    float xp = fminf(a1, b1);
    float yp = fmaxf(a3, b3);
    float o1 = fmaxf(xp, yp);
    w3 = fmaxf(o1, e2);
    w4 = fminf(o1, e2);
}

// ---------------------------------------------------------------------------
// Kernel A: per-block 95th-percentile scale (needs 4th & 5th largest |x| of
// 64). Barrier-free: 4 lanes per 64-elem block; each lane loads 4 consecutive
// float4 (warp = 8KB contiguous, coalesced), runs a Batcher selection network
// (91 FMNMX total incl. cross-lane merges, vs 204 for insertion sort — the
// alu pipe is the saturated resource), two shfl.bfly merges give block ranks
// 3,4 in all 4 lanes. Last CTA reduces scale min/max globally.
// ---------------------------------------------------------------------------
__global__ void __launch_bounds__(256) kA(const float4* __restrict__ in4,
                                          int n4, int num_blocks) {
    __shared__ float wmin[8], wmax[8];
    __shared__ float rmin[256], rmax[256];
    __shared__ int   s_last;

    const int tid  = threadIdx.x;
    const int lane = tid & 31;
    const int warp = tid >> 5;
    const int w    = blockIdx.x * 8 + warp;      // global warp id
    const int f4b  = w * 128 + lane * 4;         // 4 consecutive f4 per lane

    float4 z = make_float4(0.f, 0.f, 0.f, 0.f);
    float4 v0 = (f4b + 0 < n4) ? in4[f4b + 0] : z;
    float4 v1 = (f4b + 1 < n4) ? in4[f4b + 1] : z;
    float4 v2 = (f4b + 2 < n4) ? in4[f4b + 2] : z;
    float4 v3 = (f4b + 3 < n4) ? in4[f4b + 3] : z;

    // four sort4s on |values| (abs folds into FMNMX input modifiers)
    float p0 = fabsf(v0.x), p1 = fabsf(v0.y), p2 = fabsf(v0.z), p3 = fabsf(v0.w);
    float q0 = fabsf(v1.x), q1 = fabsf(v1.y), q2 = fabsf(v1.z), q3 = fabsf(v1.w);
    float r0 = fabsf(v2.x), r1 = fabsf(v2.y), r2 = fabsf(v2.z), r3 = fabsf(v2.w);
    float u0 = fabsf(v3.x), u1 = fabsf(v3.y), u2 = fabsf(v3.z), u3 = fabsf(v3.w);
    sort4(p0, p1, p2, p3);
    sort4(q0, q1, q2, q3);
    sort4(r0, r1, r2, r3);
    sort4(u0, u1, u2, u3);

    float A0, A1, A2, A3, A4, B0, B1, B2, B3, B4;
    merge44_top5(p0, p1, p2, p3, q0, q1, q2, q3, A0, A1, A2, A3, A4);
    merge44_top5(r0, r1, r2, r3, u0, u1, u2, u3, B0, B1, B2, B3, B4);

    float t0, t1, t2, t3, t4;
    merge55_top5(A0, A1, A2, A3, A4, B0, B1, B2, B3, B4, t0, t1, t2, t3, t4);

    // cross-lane merge xor1: full sorted-5 result needed
    const unsigned FULL = 0xFFFFFFFFu;
    {
        float b0 = __shfl_xor_sync(FULL, t0, 1);
        float b1 = __shfl_xor_sync(FULL, t1, 1);
        float b2 = __shfl_xor_sync(FULL, t2, 1);
        float b3 = __shfl_xor_sync(FULL, t3, 1);
        float b4 = __shfl_xor_sync(FULL, t4, 1);
        merge55_top5(t0, t1, t2, t3, t4, b0, b1, b2, b3, b4,
                     t0, t1, t2, t3, t4);
    }
    // cross-lane merge xor2: only ranks 3 (4th largest) & 4 (5th largest)
    float w3, w4;
    {
        float b0 = __shfl_xor_sync(FULL, t0, 2);
        float b1 = __shfl_xor_sync(FULL, t1, 2);
        float b2 = __shfl_xor_sync(FULL, t2, 2);
        float b3 = __shfl_xor_sync(FULL, t3, 2);
        float b4 = __shfl_xor_sync(FULL, t4, 2);
        merge55_r34(t0, t1, t2, t3, t4, b0, b1, b2, b3, b4, w3, w4);
    }

    // jnp.quantile linear: index = fp32(0.95*63), frac = index - 59.
    // a[59] = 5th largest = w4, a[60] = 4th largest = w3.
    const float FRAC = 0.95f * 63.0f - 59.0f;
    const float OMF  = 1.0f - FRAC;
    float s = __fadd_rn(__fmul_rn(w4, OMF), __fmul_rn(w3, FRAC));
    s = fmaxf(s, 1e-8f);

    int b = w * 8 + (lane >> 2);
    bool bvalid = (b < num_blocks);
    if (bvalid && (lane & 3) == 0) g_scales[b] = s;

    // warp reduce min/max of scales (4x duplication harmless for min/max)
    float smn = bvalid ? s : 3.402823466e38f;
    float smx = bvalid ? s : 0.0f;
    #pragma unroll
    for (int m = 16; m > 0; m >>= 1) {
        smn = fminf(smn, __shfl_xor_sync(FULL, smn, m));
        smx = fmaxf(smx, __shfl_xor_sync(FULL, smx, m));
    }
    if (lane == 0) { wmin[warp] = smn; wmax[warp] = smx; }
    __syncthreads();
    if (tid == 0) {
        float mn = wmin[0], mx = wmax[0];
        #pragma unroll
        for (int k = 1; k < 8; k++) {
            mn = fminf(mn, wmin[k]);
            mx = fmaxf(mx, wmax[k]);
        }
        __stcg(&g_pmin[blockIdx.x], mn);
        __stcg(&g_pmax[blockIdx.x], mx);
        __threadfence();
        s_last = (atomicAdd(&g_ctr, 1u) == (unsigned)(gridDim.x - 1));
    }
    __syncthreads();

    if (s_last) {                       // CTA-uniform: final global reduce
        int np = gridDim.x;
        float mn = 3.402823466e38f, mx = 0.0f;
        for (int i = tid; i < np; i += 256) {
            mn = fminf(mn, __ldcg(&g_pmin[i]));
            mx = fmaxf(mx, __ldcg(&g_pmax[i]));
        }
        rmin[tid] = mn; rmax[tid] = mx;
        __syncthreads();
        #pragma unroll
        for (int off = 128; off > 0; off >>= 1) {
            if (tid < off) {
                rmin[tid] = fminf(rmin[tid], rmin[tid + off]);
                rmax[tid] = fmaxf(rmax[tid], rmax[tid + off]);
            }
            __syncthreads();
        }
        if (tid == 0) {
            float smin = rmin[0], smax = rmax[0];
            int cond = (smax > smin);
            g_smin = smin;
            g_cond = cond;
            g_ss = cond ? __fdiv_rn(__fsub_rn(smax, smin), 255.0f) : 1.0f;
            g_ctr = 0u;                 // reset for next graph replay
        }
    }
}

// ---------------------------------------------------------------------------
// Kernel C: per-block finalize — 8-bit double-quant of scale + RN reciprocal.
// ---------------------------------------------------------------------------
__global__ void __launch_bounds__(256) kC(int num_blocks) {
    int b = blockIdx.x * 256 + threadIdx.x;
    if (b >= num_blocks) return;
    float s = g_scales[b];
    float qv = 0.0f;
    if (g_cond) {
        qv = rintf(__fdiv_rn(__fsub_rn(s, g_smin), g_ss)); // half-even = jnp.round
        qv = fminf(fmaxf(qv, 0.0f), 255.0f);
    }
    float deq = __fmul_rn(qv, g_ss);  // smin deliberately dropped (matches ref)
    float r   = __frcp_rn(s);
    g_info2[b] = make_float2(r, deq);
}

// ---------------------------------------------------------------------------
// Kernel D: quant+dequant in one read of x (partly L2-resident after kA).
// fp32 bit-grid rounding: magnitude levels {0.75,1,1.5,2,3} are the
// 1-mantissa-bit fp32 grid -> clamp |q| to [0.75,3], +0x1FFFFF (round-half-
// down = positive argmin tie rule), mask. Zero if |q|<=0.375.
// ---------------------------------------------------------------------------
__device__ __forceinline__ float qd1(float x, float r, float deq) {
    float q = __fmul_rn(x, r);
    float a = fabsf(q);
    float m = fminf(fmaxf(a, 0.75f), 3.0f);
    unsigned u = __float_as_uint(m) + 0x001FFFFFu;
    u &= 0xFFC00000u;
    float mag = (a > 0.375f) ? __uint_as_float(u) : 0.0f;
    float v = __fmul_rn(mag, deq);
    return __uint_as_float(__float_as_uint(v) |
                           (__float_as_uint(q) & 0x80000000u));
}

__global__ void __launch_bounds__(256) kD(const float4* __restrict__ in4,
                                          float4* __restrict__ out4, int n4) {
    int base = blockIdx.x * 2048 + threadIdx.x;
    #pragma unroll
    for (int k = 0; k < 8; k++) {
        int i = base + k * 256;
        if (i < n4) {
            int b = i >> 4;                 // 16 float4 per 64-elem block
            float2 nfo = g_info2[b];        // broadcast across 16 threads
            float4 x = __ldcg(&in4[i]);     // L2 hit; skip L1
            float4 o;
            o.x = qd1(x.x, nfo.x, nfo.y);
            o.y = qd1(x.y, nfo.x, nfo.y);
            o.z = qd1(x.z, nfo.x, nfo.y);
            o.w = qd1(x.w, nfo.x, nfo.y);
            __stcs(&out4[i], o);            // stream out
        }
    }
}

// Scalar tail (n % 4 != 0) — not hit for 4096x4096.
__global__ void kDtail(const float* __restrict__ in, float* __restrict__ out,
                       int start, int n) {
    int i = start + blockIdx.x * blockDim.x + threadIdx.x;
    if (i >= n) return;
    int b = i >> 6;
    float2 nfo = g_info2[b];
    out[i] = qd1(in[i], nfo.x, nfo.y);
}

extern "C" void kernel_launch(void* const* d_in, const int* in_sizes, int n_in,
                              void* d_out, int out_size) {
    const float* x = (const float*)d_in[0];
    float* out = (float*)d_out;
    int n = in_sizes[0];

    int num_blocks = (n + 63) >> 6;
    if (num_blocks > MAXB) num_blocks = MAXB;   // fixed shape fits

    // kA: 256 threads = 8 warps = 64 quant-blocks per CTA
    int gridA = (num_blocks + 63) >> 6;
    if (gridA > MAXGA) gridA = MAXGA;
    int n4 = n >> 2;

    kA<<<gridA, 256>>>((const float4*)x, n4, num_blocks);
    kC<<<(num_blocks + 255) >> 8, 256>>>(num_blocks);
    if (n4 > 0)
        kD<<<(n4 + 2047) >> 11, 256>>>((const float4*)x, (float4*)out, n4);
    int tail = n & 3;
    if (tail)
        kDtail<<<1, 32>>>(x, out, n4 << 2, n);
}

// round 9
// speedup vs baseline: 1.3622x; 1.0791x over previous
#include <cuda_runtime.h>
#include <math.h>

// x: 4096x4096 fp32 = 16,777,216 elems -> 262,144 blocks of 64.
// Single persistent kernel, 592 CTAs x 256 thr, 4 CTAs/SM guaranteed
// resident (launch_bounds) => in-kernel spin grid-barrier is safe.
#define GRID  592
#define NT    7            // tiles: ceil(4194304 f4 / (592*1024)) = 7

__device__ float    g_pmin[GRID];
__device__ float    g_pmax[GRID];
__device__ float    g_smin;
__device__ float    g_ss;
__device__ int      g_cond;
__device__ unsigned g_ctr;            // phase-1 arrivals (returns to 0)
__device__ unsigned g_done;           // finishers       (returns to 0)
__device__ volatile unsigned g_flag;  // scales ready    (returns to 0)

// ---- Batcher selection pieces (fmax/fmin only: abs folds into FMNMX) ----
__device__ __forceinline__ void ce(float& a, float& b) {
    float hi = fmaxf(a, b);
    b = fminf(a, b);
    a = hi;
}
__device__ __forceinline__ void sort4(float& s0, float& s1, float& s2, float& s3) {
    ce(s0, s1); ce(s2, s3); ce(s0, s2); ce(s1, s3); ce(s1, s2);
}
// two sorted-desc-4 -> sorted-desc top-5 (13 ops)
__device__ __forceinline__ void merge44_top5(
    float a0, float a1, float a2, float a3,
    float b0, float b1, float b2, float b3,
    float& r0, float& r1, float& r2, float& r3, float& r4) {
    float e0 = fmaxf(a0, b0), x = fminf(a0, b0);
    float y  = fmaxf(a2, b2);
    float e1 = fmaxf(x, y),  e2 = fminf(x, y);
    float o0 = fmaxf(a1, b1), xp = fminf(a1, b1);
    float yp = fmaxf(a3, b3);
    float o1 = fmaxf(xp, yp);
    r0 = e0;
    r1 = fmaxf(o0, e1); r2 = fminf(o0, e1);
    r3 = fmaxf(o1, e2); r4 = fminf(o1, e2);
}
// two sorted-desc-5 -> sorted-desc top-5 (15 ops)
__device__ __forceinline__ void merge55_top5(
    float a0, float a1, float a2, float a3, float a4,
    float b0, float b1, float b2, float b3, float b4,
    float& r0, float& r1, float& r2, float& r3, float& r4) {
    float f0 = fmaxf(a0, b0), x = fminf(a0, b0);
    float y  = fmaxf(a4, b4);
    float f1 = fmaxf(x, y);
    float g0 = fmaxf(a2, b2);
    float e1 = fmaxf(g0, f1), e2 = fminf(g0, f1);
    float o0 = fmaxf(a1, b1), xp = fminf(a1, b1);
    float yp = fmaxf(a3, b3);
    float o1 = fmaxf(xp, yp);
    r0 = f0;
    r1 = fmaxf(o0, e1); r2 = fminf(o0, e1);
    r3 = fmaxf(o1, e2); r4 = fminf(o1, e2);
}
// two sorted-desc-5 -> ranks 3 & 4 only (10 ops)
__device__ __forceinline__ void merge55_r34(
    float a0, float a1, float a2, float a3, float a4,
    float b0, float b1, float b2, float b3, float b4,
    float& w3, float& w4) {
    float x  = fminf(a0, b0);
    float y  = fmaxf(a4, b4);
    float f1 = fmaxf(x, y);
    float g0 = fmaxf(a2, b2);
    float e2 = fminf(g0, f1);
    float xp = fminf(a1, b1);
    float yp = fmaxf(a3, b3);
    float o1 = fmaxf(xp, yp);
    w3 = fmaxf(o1, e2);
    w4 = fminf(o1, e2);
}

// 4-bit code: levels {0.75,1,1.5,2,3} are the 1-mantissa-bit fp32 grid.
// clamp |q| to [0.75,3], +0x1FFFFF (round-half-down = positive argmin tie),
// exponent+msb -> level 1..5; 0 if |q|<=0.375; bit3 = sign.
__device__ __forceinline__ unsigned code1(float x, float rs) {
    float q = __fmul_rn(x, rs);
    float a = fabsf(q);
    float m = fminf(fmaxf(a, 0.75f), 3.0f);
    unsigned lv = ((__float_as_uint(m) + 0x001FFFFFu) >> 22) - 0xFCu;  // 1..5
    lv = (a > 0.375f) ? lv : 0u;
    return lv | ((__float_as_uint(q) >> 28) & 8u);
}
// decode: mag*4 in {0,3,4,6,8,12} packed as nibbles of an immediate
__device__ __forceinline__ float dec1(unsigned nib, float dq4) {
    float mag4 = (float)((0x00C86430u >> ((nib & 7u) << 2)) & 0xFu);
    float v = __fmul_rn(mag4, dq4);
    return __uint_as_float(__float_as_uint(v) | ((nib & 8u) << 28));
}

__global__ void __launch_bounds__(256, 4)
kFused(const float4* __restrict__ in4, float4* __restrict__ out4,
       int n4, int num_blocks, int ntiles) {
    // per-thread state lives in SMEM (dynamic tile indexing without local mem)
    __shared__ unsigned scode[NT][256][2];  // 4-bit codes: 16 elems/thread
    __shared__ float    ssc[NT][256];       // per-thread block scale s
    __shared__ float    sdq[NT][64];        // per-block deq*0.25
    __shared__ float    wmin[8], wmax[8];
    __shared__ float    rmin[256], rmax[256];
    __shared__ int      s_last;

    const int tid  = threadIdx.x;
    const int lane = tid & 31;
    const int warp = tid >> 5;
    const unsigned FULL = 0xFFFFFFFFu;

    float mn = 3.402823466e38f, mx = 0.0f;

    // ================= Phase 1: scales + codes (single read of x) =========
    for (int t = 0; t < ntiles; t++) {
        int chunk = (t * GRID + blockIdx.x) * 1024;        // f4 base of CTA tile
        int f4b = chunk + warp * 128 + lane * 4;           // 4 consecutive f4
        float4 z = make_float4(0.f, 0.f, 0.f, 0.f);
        float4 v0 = (f4b + 0 < n4) ? __ldcs(&in4[f4b + 0]) : z;
        float4 v1 = (f4b + 1 < n4) ? __ldcs(&in4[f4b + 1]) : z;
        float4 v2 = (f4b + 2 < n4) ? __ldcs(&in4[f4b + 2]) : z;
        float4 v3 = (f4b + 3 < n4) ? __ldcs(&in4[f4b + 3]) : z;

        float p0 = fabsf(v0.x), p1 = fabsf(v0.y), p2 = fabsf(v0.z), p3 = fabsf(v0.w);
        float q0 = fabsf(v1.x), q1 = fabsf(v1.y), q2 = fabsf(v1.z), q3 = fabsf(v1.w);
        float r0 = fabsf(v2.x), r1 = fabsf(v2.y), r2 = fabsf(v2.z), r3 = fabsf(v2.w);
        float u0 = fabsf(v3.x), u1 = fabsf(v3.y), u2 = fabsf(v3.z), u3 = fabsf(v3.w);
        sort4(p0, p1, p2, p3);
        sort4(q0, q1, q2, q3);
        sort4(r0, r1, r2, r3);
        sort4(u0, u1, u2, u3);

        float A0, A1, A2, A3, A4, B0, B1, B2, B3, B4;
        merge44_top5(p0, p1, p2, p3, q0, q1, q2, q3, A0, A1, A2, A3, A4);
        merge44_top5(r0, r1, r2, r3, u0, u1, u2, u3, B0, B1, B2, B3, B4);
        float t0, t1, t2, t3, t4;
        merge55_top5(A0, A1, A2, A3, A4, B0, B1, B2, B3, B4, t0, t1, t2, t3, t4);

        {   // cross-lane xor1: full sorted-5
            float b0 = __shfl_xor_sync(FULL, t0, 1);
            float b1 = __shfl_xor_sync(FULL, t1, 1);
            float b2 = __shfl_xor_sync(FULL, t2, 1);
            float b3 = __shfl_xor_sync(FULL, t3, 1);
            float b4 = __shfl_xor_sync(FULL, t4, 1);
            merge55_top5(t0, t1, t2, t3, t4, b0, b1, b2, b3, b4,
                         t0, t1, t2, t3, t4);
        }
        float w3, w4;
        {   // cross-lane xor2: only ranks 3 (4th largest) & 4 (5th largest)
            float b0 = __shfl_xor_sync(FULL, t0, 2);
            float b1 = __shfl_xor_sync(FULL, t1, 2);
            float b2 = __shfl_xor_sync(FULL, t2, 2);
            float b3 = __shfl_xor_sync(FULL, t3, 2);
            float b4 = __shfl_xor_sync(FULL, t4, 2);
            merge55_r34(t0, t1, t2, t3, t4, b0, b1, b2, b3, b4, w3, w4);
        }

        // jnp.quantile linear: a[59]*(1-frac)+a[60]*frac, frac=fp32(.95*63)-59
        const float FRAC = 0.95f * 63.0f - 59.0f;
        const float OMF  = 1.0f - FRAC;
        float s = __fadd_rn(__fmul_rn(w4, OMF), __fmul_rn(w3, FRAC));
        s = fmaxf(s, 1e-8f);
        ssc[t][tid] = s;

        float rs = __frcp_rn(s);
        scode[t][tid][0] =  code1(v0.x, rs)        | (code1(v0.y, rs) << 4)
                         | (code1(v0.z, rs) << 8)  | (code1(v0.w, rs) << 12)
                         | (code1(v1.x, rs) << 16) | (code1(v1.y, rs) << 20)
                         | (code1(v1.z, rs) << 24) | (code1(v1.w, rs) << 28);
        scode[t][tid][1] =  code1(v2.x, rs)        | (code1(v2.y, rs) << 4)
                         | (code1(v2.z, rs) << 8)  | (code1(v2.w, rs) << 12)
                         | (code1(v3.x, rs) << 16) | (code1(v3.y, rs) << 20)
                         | (code1(v3.z, rs) << 24) | (code1(v3.w, rs) << 28);

        int b = (chunk >> 4) + warp * 8 + (lane >> 2);
        if (b < num_blocks) { mn = fminf(mn, s); mx = fmaxf(mx, s); }
    }

    // CTA reduce min/max of scales
    #pragma unroll
    for (int m = 16; m > 0; m >>= 1) {
        mn = fminf(mn, __shfl_xor_sync(FULL, mn, m));
        mx = fmaxf(mx, __shfl_xor_sync(FULL, mx, m));
    }
    if (lane == 0) { wmin[warp] = mn; wmax[warp] = mx; }
    __syncthreads();
    if (tid == 0) {
        float cmn = wmin[0], cmx = wmax[0];
        #pragma unroll
        for (int k = 1; k < 8; k++) {
            cmn = fminf(cmn, wmin[k]);
            cmx = fmaxf(cmx, wmax[k]);
        }
        __stcg(&g_pmin[blockIdx.x], cmn);
        __stcg(&g_pmax[blockIdx.x], cmx);
        __threadfence();
        s_last = (atomicAdd(&g_ctr, 1u) == (unsigned)(gridDim.x - 1));
    }
    __syncthreads();

    // ================= Grid barrier: last CTA publishes =====================
    if (s_last) {
        float fmn = 3.402823466e38f, fmx = 0.0f;
        for (int i = tid; i < GRID; i += 256) {
            fmn = fminf(fmn, __ldcg(&g_pmin[i]));
            fmx = fmaxf(fmx, __ldcg(&g_pmax[i]));
        }
        rmin[tid] = fmn; rmax[tid] = fmx;
        __syncthreads();
        #pragma unroll
        for (int off = 128; off > 0; off >>= 1) {
            if (tid < off) {
                rmin[tid] = fminf(rmin[tid], rmin[tid + off]);
                rmax[tid] = fmaxf(rmax[tid], rmax[tid + off]);
            }
            __syncthreads();
        }
        if (tid == 0) {
            float smin = rmin[0], smax = rmax[0];
            int cond = (smax > smin);
            g_smin = smin;
            g_cond = cond;
            g_ss = cond ? __fdiv_rn(__fsub_rn(smax, smin), 255.0f) : 1.0f;
            g_ctr = 0u;                   // reset for next graph replay
            __threadfence();
            g_flag = 1u;
        }
        __syncthreads();
    } else {
        if (tid == 0) {
            while (g_flag == 0u) __nanosleep(64);
            __threadfence();
        }
        __syncthreads();
    }

    const float smin = g_smin;
    const float ss   = g_ss;
    const int   cond = g_cond;

    // Precompute per-block deq*0.25 once (64 blocks per CTA-tile)
    for (int t = 0; t < ntiles; t++) {
        if (tid < 64) {
            // producer thread for block b: warp b>>3, lane (b&7)*4
            float s = ssc[t][((tid >> 3) << 5) + ((tid & 7) << 2)];
            float qv = 0.0f;
            if (cond) {
                qv = rintf(__fdiv_rn(__fsub_rn(s, smin), ss)); // half-even
                qv = fminf(fmaxf(qv, 0.0f), 255.0f);
            }
            sdq[t][tid] = __fmul_rn(qv, ss) * 0.25f;  // smin dropped (ref)
        }
    }
    __syncthreads();

    // ================= Phase 2: decode + coalesced write ===================
    for (int t = 0; t < ntiles; t++) {
        int chunk = (t * GRID + blockIdx.x) * 1024;
        #pragma unroll
        for (int k = 0; k < 4; k++) {
            int o = tid + k * 256;             // f4 offset within CTA tile
            int g = chunk + o;
            if (g < n4) {
                unsigned wbits = scode[t][o >> 2][(o >> 1) & 1];
                unsigned h = wbits >> ((o & 1) << 4);   // 16 bits = 4 nibbles
                float dq4 = sdq[t][o >> 4];
                float4 ov;
                ov.x = dec1(h,       dq4);
                ov.y = dec1(h >> 4,  dq4);
                ov.z = dec1(h >> 8,  dq4);
                ov.w = dec1(h >> 12, dq4);
                __stcs(&out4[g], ov);
            }
        }
    }

    // ================= Cleanup: last finisher resets flag ==================
    if (tid == 0) {
        __threadfence();
        if (atomicAdd(&g_done, 1u) == (unsigned)(gridDim.x - 1)) {
            g_done = 0u;
            g_flag = 0u;
        }
    }
}

extern "C" void kernel_launch(void* const* d_in, const int* in_sizes, int n_in,
                              void* d_out, int out_size) {
    const float* x = (const float*)d_in[0];
    float* out = (float*)d_out;
    int n = in_sizes[0];

    int n4 = n >> 2;                     // n multiple of 4 for this problem
    int num_blocks = (n + 63) >> 6;
    int per_tile = GRID * 1024;          // f4 per tile
    int ntiles = (n4 + per_tile - 1) / per_tile;
    if (ntiles > NT) ntiles = NT;        // fixed shape needs exactly 7

    kFused<<<GRID, 256>>>((const float4*)x, (float4*)out, n4, num_blocks,
                          ntiles);
}